// round 14
// baseline (speedup 1.0000x reference)
#include <cuda_runtime.h>

// PhonologicalLoopMemory — FINAL kernel (family best: 12.45us; mean ~12.8us).
//
// Algebraic reduction of the reference (never materializes the 2 GiB decayed
// buffer):
//   out[b] = concat(recent[0..3], rehearsal), segment = 32768 f32 = 8192 float4.
//   recent[0] = rehearsal = features[b]   (buf[old_pos] was just set -> undecayed)
//   recent[j] = valid_j ? 0.9 * feature_buffer[b, (pos[b]-j) & 63] : 0, j=1..3
//   valid_j   = buffer_filled[b] || (j <= pos[b])
//   ((pos-j) mod 64 != pos for j in 1..3, so the .set never aliases these reads)
//
// Roofline-bound: 72 MiB is the information-theoretic traffic floor (inputs
// read once, outputs written once; features read ONCE, fanned out to output
// segments 0 and 4). Measured ~6 TB/s effective = the B300 path-independent
// chip LTS throughput cap (~6300 B/cyc). Across 14 benches, duration was
// invariant to occupancy (31-98%), unroll (1-16), block size (256/512), grid
// shape, access width (128/256-bit), and L2 eviction policy (evict_last and
// evict_first both neutral). Only byte-count reduction ever moved the mean.

#define SEG_F4   8192   // 32768 floats / 4
#define BUF_LEN  64
#define NSEG     5
#define UNROLL   8
#define TPB      256

__global__ __launch_bounds__(TPB) void phono_kernel(
    const float4* __restrict__ feat,          // [B, 8192]
    const float4* __restrict__ fbuf,          // [B, 64, 8192]
    const int*    __restrict__ cur_pos,       // [B]
    const int*    __restrict__ filled,        // [B] int32 (bool upcast)
    float4* __restrict__ out)                 // [B, 5, 8192]
{
    const int by   = blockIdx.y;              // b*4 + j, j in 0..3 (j==0 covers segs 0 and 4)
    const int b    = by >> 2;
    const int j    = by & 3;
    const int base = blockIdx.x * (TPB * UNROLL) + threadIdx.x;

    float4 v[UNROLL];
    float4* dst0 = out + ((size_t)b * NSEG + j) * SEG_F4 + base;

    if (j == 0) {
        // features -> recent[0] AND rehearsal (seg 4): one read, two writes.
        const float4* src = feat + (size_t)b * SEG_F4 + base;
        #pragma unroll
        for (int k = 0; k < UNROLL; k++) v[k] = src[k * TPB];

        float4* dst4 = out + ((size_t)b * NSEG + 4) * SEG_F4 + base;
        #pragma unroll
        for (int k = 0; k < UNROLL; k++) dst0[k * TPB] = v[k];
        #pragma unroll
        for (int k = 0; k < UNROLL; k++) dst4[k * TPB] = v[k];
        return;
    }

    const int p = cur_pos[b];
    const bool valid = (filled[b] != 0) || (j <= p);
    if (valid) {
        const int slot = (p - j + BUF_LEN) & (BUF_LEN - 1);
        const float4* src = fbuf + ((size_t)b * BUF_LEN + slot) * SEG_F4 + base;
        #pragma unroll
        for (int k = 0; k < UNROLL; k++) v[k] = src[k * TPB];
        #pragma unroll
        for (int k = 0; k < UNROLL; k++) {
            v[k].x *= 0.9f; v[k].y *= 0.9f; v[k].z *= 0.9f; v[k].w *= 0.9f;
        }
    } else {
        #pragma unroll
        for (int k = 0; k < UNROLL; k++) v[k] = make_float4(0.f, 0.f, 0.f, 0.f);
    }
    #pragma unroll
    for (int k = 0; k < UNROLL; k++) dst0[k * TPB] = v[k];
}

extern "C" void kernel_launch(void* const* d_in, const int* in_sizes, int n_in,
                              void* d_out, int out_size)
{
    const float4* feat   = (const float4*)d_in[0];
    const float4* fbuf   = (const float4*)d_in[1];
    const int*    pos    = (const int*)d_in[2];
    const int*    filled = (const int*)d_in[3];
    float4*       out    = (float4*)d_out;

    const int batch = in_sizes[2];                    // 64
    dim3 block(TPB);
    dim3 grid(SEG_F4 / (TPB * UNROLL), batch * 4);    // (4, 256) = 1024 blocks
    phono_kernel<<<grid, block>>>(feat, fbuf, pos, filled, out);
}

// round 15
// speedup vs baseline: 1.0543x; 1.0543x over previous
#include <cuda_runtime.h>

// PhonologicalLoopMemory — converged minimal-traffic kernel (TPB=128 family sample).
//
// Algebraic reduction (no 2 GiB decayed-buffer materialization):
//   out[b] = concat(recent[0..3], rehearsal), segment = 32768 f32 = 8192 float4.
//   recent[0] = rehearsal = features[b]   (buf[old_pos] just set -> undecayed)
//   recent[j] = valid_j ? 0.9 * feature_buffer[b, (pos[b]-j) & 63] : 0, j=1..3
//   valid_j   = buffer_filled[b] || (j <= pos[b])
//
// Roofline-bound: 72 MiB = traffic floor (inputs read once, outputs written
// once; features read ONCE, fanned to segments 0 and 4). ~6 TB/s effective =
// path-independent chip fabric cap. 15 benches: invariant to occupancy
// (31-98%), unroll (1-16), block size, grid shape, access width, L2 policy.

#define SEG_F4   8192   // 32768 floats / 4
#define BUF_LEN  64
#define NSEG     5
#define UNROLL   8
#define TPB      128

__global__ __launch_bounds__(TPB) void phono_kernel(
    const float4* __restrict__ feat,          // [B, 8192]
    const float4* __restrict__ fbuf,          // [B, 64, 8192]
    const int*    __restrict__ cur_pos,       // [B]
    const int*    __restrict__ filled,        // [B] int32 (bool upcast)
    float4* __restrict__ out)                 // [B, 5, 8192]
{
    const int by   = blockIdx.y;              // b*4 + j, j in 0..3 (j==0 covers segs 0 and 4)
    const int b    = by >> 2;
    const int j    = by & 3;
    const int base = blockIdx.x * (TPB * UNROLL) + threadIdx.x;

    float4 v[UNROLL];
    float4* dst0 = out + ((size_t)b * NSEG + j) * SEG_F4 + base;

    if (j == 0) {
        // features -> recent[0] AND rehearsal (seg 4): one read, two writes.
        const float4* src = feat + (size_t)b * SEG_F4 + base;
        #pragma unroll
        for (int k = 0; k < UNROLL; k++) v[k] = src[k * TPB];

        float4* dst4 = out + ((size_t)b * NSEG + 4) * SEG_F4 + base;
        #pragma unroll
        for (int k = 0; k < UNROLL; k++) dst0[k * TPB] = v[k];
        #pragma unroll
        for (int k = 0; k < UNROLL; k++) dst4[k * TPB] = v[k];
        return;
    }

    const int p = cur_pos[b];
    const bool valid = (filled[b] != 0) || (j <= p);
    if (valid) {
        const int slot = (p - j + BUF_LEN) & (BUF_LEN - 1);
        const float4* src = fbuf + ((size_t)b * BUF_LEN + slot) * SEG_F4 + base;
        #pragma unroll
        for (int k = 0; k < UNROLL; k++) v[k] = src[k * TPB];
        #pragma unroll
        for (int k = 0; k < UNROLL; k++) {
            v[k].x *= 0.9f; v[k].y *= 0.9f; v[k].z *= 0.9f; v[k].w *= 0.9f;
        }
    } else {
        #pragma unroll
        for (int k = 0; k < UNROLL; k++) v[k] = make_float4(0.f, 0.f, 0.f, 0.f);
    }
    #pragma unroll
    for (int k = 0; k < UNROLL; k++) dst0[k * TPB] = v[k];
}

extern "C" void kernel_launch(void* const* d_in, const int* in_sizes, int n_in,
                              void* d_out, int out_size)
{
    const float4* feat   = (const float4*)d_in[0];
    const float4* fbuf   = (const float4*)d_in[1];
    const int*    pos    = (const int*)d_in[2];
    const int*    filled = (const int*)d_in[3];
    float4*       out    = (float4*)d_out;

    const int batch = in_sizes[2];                    // 64
    dim3 block(TPB);
    dim3 grid(SEG_F4 / (TPB * UNROLL), batch * 4);    // (8, 256) = 2048 blocks
    phono_kernel<<<grid, block>>>(feat, fbuf, pos, filled, out);
}